// round 1
// baseline (speedup 1.0000x reference)
#include <cuda_runtime.h>
#include <math.h>
#include <stdint.h>

// ---------------------------------------------------------------------------
// Problem constants (from reference setup)
// ---------------------------------------------------------------------------
#define NE_MAX 30000
#define NU_MAX 200000
#define NS_MAX 20000
#define ESE_MAX 30000
#define EUE_MAX 1000000

// ---------------------------------------------------------------------------
// Device scratch (static globals; no allocation at launch time)
// ---------------------------------------------------------------------------
__device__ float g_WeT[768 * 128];          // W_email transposed (k-major)
__device__ float g_Wu[72 * 128];            // url KAN concat weight, k-major
__device__ float g_Wsn[16 * 128];           // sender KAN concat weight (padded), k-major
__device__ float g_Wc[384 * 128];           // combined SAGE weight, k-major
__device__ float g_bc[128];                 // combined SAGE bias
__device__ float g_Fu[(size_t)NU_MAX * 72]; // url features [silu(8), bases(64)]
__device__ float g_Fs[(size_t)NS_MAX * 16]; // sender features padded
__device__ float g_u[(size_t)NU_MAX * 128]; // url embeddings (tanh)
__device__ float g_s[(size_t)NS_MAX * 128]; // sender embeddings (tanh)
__device__ float g_X[(size_t)NE_MAX * 384]; // [agg_se | agg_ue | e]
__device__ float g_C[(size_t)NE_MAX * 256]; // combined = [email_h | e]
__device__ int g_cnt_se[NE_MAX];
__device__ int g_cnt_ue[NE_MAX];
__device__ int g_off[NE_MAX + 1];
__device__ int g_wp[NE_MAX];
__device__ int g_sorted[EUE_MAX];
__device__ float g_sums[256];
__device__ float g_sumsq[256];
__device__ float g_scale[256];
__device__ float g_shift[256];

// ---------------------------------------------------------------------------
// B-spline (grid_size=5, spline_order=3 -> 8 bases, 12 knots on [-2.2, 2.2])
// Mirrors the JAX Cox-de Boor recursion exactly (fp32).
// ---------------------------------------------------------------------------
__device__ __forceinline__ float gknot(int i) {
    return (float)(i - 3) * 0.4f - 1.0f;
}

__device__ __forceinline__ void bspline8(float x, float* out) {
    float b[11];
#pragma unroll
    for (int i = 0; i < 11; i++) {
        b[i] = (x >= gknot(i) && x < gknot(i + 1)) ? 1.0f : 0.0f;
    }
#pragma unroll
    for (int j = 1; j <= 3; j++) {
#pragma unroll
        for (int i = 0; i <= 10 - j; i++) {
            float d1 = gknot(i + j) - gknot(i);
            float d2 = gknot(i + j + 1) - gknot(i + 1);
            b[i] = (x - gknot(i)) / d1 * b[i] + (gknot(i + j + 1) - x) / d2 * b[i + 1];
        }
    }
#pragma unroll
    for (int i = 0; i < 8; i++) out[i] = b[i];
}

__device__ __forceinline__ float silu(float x) {
    return x / (1.0f + expf(-x));
}

// ---------------------------------------------------------------------------
// Generic SGEMM: C[M,128] = act(A[M,K] @ B[K,128] + bias)
// B is k-major (row k contiguous over 128 cols). BM=128 BN=128 BK=8, 8x8/thread.
// Optional second destination C2 (for writing e to both X and C).
// ---------------------------------------------------------------------------
template <int ACT>  // 0=none 1=tanh 2=lrelu(0.2)
__global__ void sgemm128(const float* __restrict__ A, const float* __restrict__ B,
                         const float* __restrict__ bias,
                         float* C, int ldc, float* C2, int ldc2,
                         int M, int K) {
    __shared__ __align__(16) float As[8][128];
    __shared__ __align__(16) float Bs[8][128];

    int bm = blockIdx.x * 128;
    int tid = threadIdx.x;             // 256 threads
    int tx = tid % 16;                 // col tile 0..15
    int ty = tid / 16;                 // row tile 0..15

    float acc[8][8];
#pragma unroll
    for (int i = 0; i < 8; i++)
#pragma unroll
        for (int j = 0; j < 8; j++) acc[i][j] = 0.0f;

    int a_row = tid >> 1;              // 0..127
    int a_kq = (tid & 1) * 4;          // 0 or 4
    int b_k = tid >> 5;                // 0..7
    int b_col = (tid & 31) * 4;

    for (int k0 = 0; k0 < K; k0 += 8) {
        int gr = bm + a_row;
        float4 av = make_float4(0.f, 0.f, 0.f, 0.f);
        if (gr < M) av = *(const float4*)(A + (size_t)gr * K + k0 + a_kq);
        As[a_kq + 0][a_row] = av.x;
        As[a_kq + 1][a_row] = av.y;
        As[a_kq + 2][a_row] = av.z;
        As[a_kq + 3][a_row] = av.w;

        float4 bv = *(const float4*)(B + (size_t)(k0 + b_k) * 128 + b_col);
        *(float4*)&Bs[b_k][b_col] = bv;
        __syncthreads();

#pragma unroll
        for (int k = 0; k < 8; k++) {
            float a[8], b[8];
#pragma unroll
            for (int i = 0; i < 8; i++) a[i] = As[k][ty * 8 + i];
#pragma unroll
            for (int j = 0; j < 8; j++) b[j] = Bs[k][tx * 8 + j];
#pragma unroll
            for (int i = 0; i < 8; i++)
#pragma unroll
                for (int j = 0; j < 8; j++) acc[i][j] += a[i] * b[j];
        }
        __syncthreads();
    }

#pragma unroll
    for (int i = 0; i < 8; i++) {
        int r = bm + ty * 8 + i;
        if (r >= M) continue;
#pragma unroll
        for (int j = 0; j < 8; j += 4) {
            int c = tx * 8 + j;
            float4 v;
            v.x = acc[i][j + 0];
            v.y = acc[i][j + 1];
            v.z = acc[i][j + 2];
            v.w = acc[i][j + 3];
            if (bias) {
                v.x += bias[c + 0]; v.y += bias[c + 1];
                v.z += bias[c + 2]; v.w += bias[c + 3];
            }
            if (ACT == 1) {
                v.x = tanhf(v.x); v.y = tanhf(v.y);
                v.z = tanhf(v.z); v.w = tanhf(v.w);
            } else if (ACT == 2) {
                v.x = v.x >= 0.f ? v.x : 0.2f * v.x;
                v.y = v.y >= 0.f ? v.y : 0.2f * v.y;
                v.z = v.z >= 0.f ? v.z : 0.2f * v.z;
                v.w = v.w >= 0.f ? v.w : 0.2f * v.w;
            }
            *(float4*)(C + (size_t)r * ldc + c) = v;
            if (C2) *(float4*)(C2 + (size_t)r * ldc2 + c) = v;
        }
    }
}

// ---------------------------------------------------------------------------
// Prep kernels (weight reshaping)
// ---------------------------------------------------------------------------
__global__ void prep_email_w(const float* __restrict__ W, float* __restrict__ Wt) {
    int idx = blockIdx.x * blockDim.x + threadIdx.x;
    if (idx < 768 * 128) {
        int k = idx / 128, o = idx % 128;
        Wt[idx] = W[o * 768 + k];
    }
}

__global__ void prep_url_w(const float* __restrict__ bw, const float* __restrict__ sw,
                           float* __restrict__ Wt) {
    int idx = blockIdx.x * blockDim.x + threadIdx.x;
    if (idx < 72 * 128) {
        int j = idx / 128, o = idx % 128;
        Wt[idx] = (j < 8) ? bw[o * 8 + j] : sw[o * 64 + (j - 8)];
    }
}

__global__ void prep_snd_w(const float* __restrict__ bw, const float* __restrict__ sw,
                           float* __restrict__ Wt) {
    int idx = blockIdx.x * blockDim.x + threadIdx.x;
    if (idx < 16 * 128) {
        int j = idx / 128, o = idx % 128;
        float v = 0.0f;
        if (j < 1) v = bw[o];
        else if (j < 9) v = sw[o * 8 + (j - 1)];
        Wt[idx] = v;
    }
}

__global__ void prep_comb_w(const float* __restrict__ wlse, const float* __restrict__ wlue,
                            const float* __restrict__ wrse, const float* __restrict__ wrue,
                            const float* __restrict__ blse, const float* __restrict__ blue,
                            float* __restrict__ Wt, float* __restrict__ bc) {
    int idx = blockIdx.x * blockDim.x + threadIdx.x;
    if (idx < 384 * 128) {
        int k = idx / 128, o = idx % 128;
        float v;
        if (k < 128) v = wlse[o * 128 + k];
        else if (k < 256) v = wlue[o * 128 + (k - 128)];
        else v = wrse[o * 128 + (k - 256)] + wrue[o * 128 + (k - 256)];
        Wt[idx] = 0.5f * v;
    }
    if (idx < 128) bc[idx] = 0.5f * (blse[idx] + blue[idx]);
}

// ---------------------------------------------------------------------------
// KAN feature construction
// ---------------------------------------------------------------------------
__global__ void feat_url(const float* __restrict__ x, float* __restrict__ F, int n) {
    int gid = blockIdx.x * blockDim.x + threadIdx.x;
    if (gid < n * 8) {
        int nd = gid / 8, i = gid % 8;
        float v = x[gid];
        float* f = F + (size_t)nd * 72;
        f[i] = silu(v);
        float bs[8];
        bspline8(v, bs);
#pragma unroll
        for (int b = 0; b < 8; b++) f[8 + i * 8 + b] = bs[b];
    }
}

__global__ void feat_snd(const float* __restrict__ x, float* __restrict__ F, int n) {
    int gid = blockIdx.x * blockDim.x + threadIdx.x;
    if (gid < n) {
        float v = x[gid];
        float* f = F + (size_t)gid * 16;
        f[0] = silu(v);
        float bs[8];
        bspline8(v, bs);
#pragma unroll
        for (int b = 0; b < 8; b++) f[1 + b] = bs[b];
#pragma unroll
        for (int j = 9; j < 16; j++) f[j] = 0.0f;
    }
}

// ---------------------------------------------------------------------------
// SE aggregation: atomics (only 30k edges)
// ---------------------------------------------------------------------------
__global__ void zero_X_se(float* __restrict__ X, int n) {
    int idx = blockIdx.x * blockDim.x + threadIdx.x;
    int tot = n * 128;
    if (idx < tot) {
        int r = idx >> 7, c = idx & 127;
        X[(size_t)r * 384 + c] = 0.0f;
    }
}

__global__ void se_agg(const float* __restrict__ sfeat, const int* __restrict__ src,
                       const int* __restrict__ dst, int E, float* __restrict__ X,
                       int* __restrict__ cnt) {
    int w = (blockIdx.x * blockDim.x + threadIdx.x) >> 5;
    int lane = threadIdx.x & 31;
    int nw = (gridDim.x * blockDim.x) >> 5;
    for (int e = w; e < E; e += nw) {
        int sid = src[e];
        int did = dst[e];
#pragma unroll
        for (int q = 0; q < 4; q++) {
            int c = q * 32 + lane;
            float v = sfeat[(size_t)sid * 128 + c];
            atomicAdd(&X[(size_t)did * 384 + c], v);
        }
        if (lane == 0) atomicAdd(&cnt[did], 1);
    }
}

__global__ void norm_se(float* __restrict__ X, const int* __restrict__ cnt, int n) {
    int idx = blockIdx.x * blockDim.x + threadIdx.x;
    int tot = n * 128;
    if (idx < tot) {
        int r = idx >> 7, c = idx & 127;
        int k = cnt[r];
        X[(size_t)r * 384 + c] *= 1.0f / (float)(k > 0 ? k : 1);
    }
}

// ---------------------------------------------------------------------------
// UE aggregation: CSR bucketing (no float atomics)
// ---------------------------------------------------------------------------
__global__ void hist_kernel(const int* __restrict__ dst, int E, int* __restrict__ cnt) {
    int gid = blockIdx.x * blockDim.x + threadIdx.x;
    if (gid < E) atomicAdd(&cnt[dst[gid]], 1);
}

__global__ void scan_excl(const int* __restrict__ in, int* __restrict__ out, int n) {
    __shared__ int sm[1024];
    __shared__ int s_carry;
    if (threadIdx.x == 0) s_carry = 0;
    __syncthreads();
    for (int base = 0; base < n; base += 1024) {
        int i = base + threadIdx.x;
        int v = (i < n) ? in[i] : 0;
        sm[threadIdx.x] = v;
        __syncthreads();
        for (int d = 1; d < 1024; d <<= 1) {
            int t = (threadIdx.x >= d) ? sm[threadIdx.x - d] : 0;
            __syncthreads();
            sm[threadIdx.x] += t;
            __syncthreads();
        }
        int incl = sm[threadIdx.x];
        int carry = s_carry;
        if (i < n) out[i] = carry + incl - v;
        __syncthreads();
        if (threadIdx.x == 0) s_carry = carry + sm[1023];
        __syncthreads();
    }
    if (threadIdx.x == 0) out[n] = s_carry;
}

__global__ void copy_int(const int* __restrict__ a, int* __restrict__ b, int n) {
    int gid = blockIdx.x * blockDim.x + threadIdx.x;
    if (gid < n) b[gid] = a[gid];
}

__global__ void bucket_kernel(const int* __restrict__ src, const int* __restrict__ dst,
                              int E, int* __restrict__ wp, int* __restrict__ sorted) {
    int gid = blockIdx.x * blockDim.x + threadIdx.x;
    if (gid < E) {
        int p = atomicAdd(&wp[dst[gid]], 1);
        sorted[p] = src[gid];
    }
}

__global__ void ue_agg(const float* __restrict__ u, const int* __restrict__ sorted,
                       const int* __restrict__ off, int ndst, float* __restrict__ X) {
    int w = (blockIdx.x * blockDim.x + threadIdx.x) >> 5;
    int lane = threadIdx.x & 31;
    int nw = (gridDim.x * blockDim.x) >> 5;
    for (int d = w; d < ndst; d += nw) {
        int a = off[d], b = off[d + 1];
        float4 acc = make_float4(0.f, 0.f, 0.f, 0.f);
        for (int e = a; e < b; e++) {
            int sid = sorted[e];
            float4 v = *(const float4*)(u + (size_t)sid * 128 + lane * 4);
            acc.x += v.x; acc.y += v.y; acc.z += v.z; acc.w += v.w;
        }
        float inv = 1.0f / (float)((b - a) > 0 ? (b - a) : 1);
        float4 o4 = make_float4(acc.x * inv, acc.y * inv, acc.z * inv, acc.w * inv);
        *(float4*)(X + (size_t)d * 384 + 128 + lane * 4) = o4;
    }
}

// ---------------------------------------------------------------------------
// BatchNorm stats + finalize
// ---------------------------------------------------------------------------
__global__ void bn_stats(const float* __restrict__ C, int n,
                         float* __restrict__ sums, float* __restrict__ sumsq) {
    int c = threadIdx.x;  // 256 threads
    float s = 0.f, q = 0.f;
    for (int r = blockIdx.x; r < n; r += gridDim.x) {
        float v = C[(size_t)r * 256 + c];
        s += v;
        q += v * v;
    }
    atomicAdd(&sums[c], s);
    atomicAdd(&sumsq[c], q);
}

__global__ void bn_finalize(const float* __restrict__ sums, const float* __restrict__ sumsq,
                            const float* __restrict__ gamma, const float* __restrict__ beta,
                            float* __restrict__ scale, float* __restrict__ shift, float invn) {
    int c = threadIdx.x;
    float m = sums[c] * invn;
    float var = sumsq[c] * invn - m * m;
    float sc = gamma[c] / sqrtf(var + 1e-5f);
    scale[c] = sc;
    shift[c] = beta[c] - m * sc;
}

// ---------------------------------------------------------------------------
// Classifier KAN: warp per node, 256 inputs -> 2 outputs
// ---------------------------------------------------------------------------
__global__ void classifier(const float* __restrict__ C, const float* __restrict__ scale,
                           const float* __restrict__ shift, const float* __restrict__ cb,
                           const float* __restrict__ cs, float* __restrict__ out, int n) {
    int w = (blockIdx.x * blockDim.x + threadIdx.x) >> 5;
    int lane = threadIdx.x & 31;
    int nw = (gridDim.x * blockDim.x) >> 5;
    for (int r = w; r < n; r += nw) {
        float a0 = 0.f, a1 = 0.f;
#pragma unroll
        for (int q = 0; q < 8; q++) {
            int i = q * 32 + lane;
            float x = C[(size_t)r * 256 + i];
            x = x * scale[i] + shift[i];
            float sl = silu(x);
            float bs[8];
            bspline8(x, bs);
            a0 += sl * __ldg(&cb[i]);
            a1 += sl * __ldg(&cb[256 + i]);
            const float* w0 = cs + i * 8;
            const float* w1 = cs + 2048 + i * 8;
#pragma unroll
            for (int b = 0; b < 8; b++) {
                a0 += bs[b] * __ldg(&w0[b]);
                a1 += bs[b] * __ldg(&w1[b]);
            }
        }
#pragma unroll
        for (int sft = 16; sft > 0; sft >>= 1) {
            a0 += __shfl_down_sync(0xFFFFFFFFu, a0, sft);
            a1 += __shfl_down_sync(0xFFFFFFFFu, a1, sft);
        }
        if (lane == 0) {
            out[(size_t)r * 2 + 0] = a0;
            out[(size_t)r * 2 + 1] = a1;
        }
    }
}

// ---------------------------------------------------------------------------
// Launch
// ---------------------------------------------------------------------------
static inline unsigned cdiv(unsigned a, unsigned b) { return (a + b - 1) / b; }

extern "C" void kernel_launch(void* const* d_in, const int* in_sizes, int n_in,
                              void* d_out, int out_size) {
    const float* email_x = (const float*)d_in[0];
    const float* url_x = (const float*)d_in[1];
    const float* sender_x = (const float*)d_in[2];
    const float* W_email = (const float*)d_in[3];
    const float* b_email = (const float*)d_in[4];
    const float* url_base_w = (const float*)d_in[5];
    const float* url_spline_w = (const float*)d_in[6];
    const float* snd_base_w = (const float*)d_in[7];
    const float* snd_spline_w = (const float*)d_in[8];
    const float* Wl_se = (const float*)d_in[9];
    const float* bl_se = (const float*)d_in[10];
    const float* Wr_se = (const float*)d_in[11];
    // d_in[12..14]: Wl_eu, bl_eu, Wr_eu -- dead (out_eu unused downstream)
    const float* Wl_ue = (const float*)d_in[15];
    const float* bl_ue = (const float*)d_in[16];
    const float* Wr_ue = (const float*)d_in[17];
    const float* bn_gamma = (const float*)d_in[18];
    const float* bn_beta = (const float*)d_in[19];
    const float* cls_base_w = (const float*)d_in[20];
    const float* cls_spline_w = (const float*)d_in[21];
    const int* ei_se_src = (const int*)d_in[22];
    const int* ei_se_dst = (const int*)d_in[23];
    // d_in[24..25]: ei_eu -- dead
    const int* ei_ue_src = (const int*)d_in[26];
    const int* ei_ue_dst = (const int*)d_in[27];

    int N_E = in_sizes[0] / 768;
    int N_U = in_sizes[1] / 8;
    int N_S = in_sizes[2];
    int E_SE = in_sizes[22];
    int E_UE = in_sizes[26];

    float* out = (float*)d_out;

    // Resolve device-global scratch addresses
    float *WeT, *Wu, *Wsn, *Wc, *bc, *Fu, *Fs, *ubuf, *sbuf, *X, *C;
    float *sums, *sumsq, *scale, *shift;
    int *cnt_se, *cnt_ue, *off, *wp, *sorted;
    cudaGetSymbolAddress((void**)&WeT, g_WeT);
    cudaGetSymbolAddress((void**)&Wu, g_Wu);
    cudaGetSymbolAddress((void**)&Wsn, g_Wsn);
    cudaGetSymbolAddress((void**)&Wc, g_Wc);
    cudaGetSymbolAddress((void**)&bc, g_bc);
    cudaGetSymbolAddress((void**)&Fu, g_Fu);
    cudaGetSymbolAddress((void**)&Fs, g_Fs);
    cudaGetSymbolAddress((void**)&ubuf, g_u);
    cudaGetSymbolAddress((void**)&sbuf, g_s);
    cudaGetSymbolAddress((void**)&X, g_X);
    cudaGetSymbolAddress((void**)&C, g_C);
    cudaGetSymbolAddress((void**)&sums, g_sums);
    cudaGetSymbolAddress((void**)&sumsq, g_sumsq);
    cudaGetSymbolAddress((void**)&scale, g_scale);
    cudaGetSymbolAddress((void**)&shift, g_shift);
    cudaGetSymbolAddress((void**)&cnt_se, g_cnt_se);
    cudaGetSymbolAddress((void**)&cnt_ue, g_cnt_ue);
    cudaGetSymbolAddress((void**)&off, g_off);
    cudaGetSymbolAddress((void**)&wp, g_wp);
    cudaGetSymbolAddress((void**)&sorted, g_sorted);

    // 0. zero accumulators
    cudaMemsetAsync(cnt_se, 0, (size_t)N_E * sizeof(int), 0);
    cudaMemsetAsync(cnt_ue, 0, (size_t)N_E * sizeof(int), 0);
    cudaMemsetAsync(sums, 0, 256 * sizeof(float), 0);
    cudaMemsetAsync(sumsq, 0, 256 * sizeof(float), 0);
    zero_X_se<<<cdiv(N_E * 128, 256), 256>>>(X, N_E);

    // 1. weight prep
    prep_email_w<<<cdiv(768 * 128, 256), 256>>>(W_email, WeT);
    prep_url_w<<<cdiv(72 * 128, 256), 256>>>(url_base_w, url_spline_w, Wu);
    prep_snd_w<<<cdiv(16 * 128, 256), 256>>>(snd_base_w, snd_spline_w, Wsn);
    prep_comb_w<<<cdiv(384 * 128, 256), 256>>>(Wl_se, Wl_ue, Wr_se, Wr_ue, bl_se, bl_ue, Wc, bc);

    // 2. KAN features
    feat_url<<<cdiv(N_U * 8, 256), 256>>>(url_x, Fu, N_U);
    feat_snd<<<cdiv(N_S, 256), 256>>>(sender_x, Fs, N_S);

    // 3. embeddings (tanh GEMMs)
    // e -> X[:,256:384] and C[:,128:256]
    sgemm128<1><<<cdiv(N_E, 128), 256>>>(email_x, WeT, b_email,
                                         X + 256, 384, C + 128, 256, N_E, 768);
    sgemm128<1><<<cdiv(N_U, 128), 256>>>(Fu, Wu, (const float*)nullptr,
                                         ubuf, 128, (float*)nullptr, 0, N_U, 72);
    sgemm128<1><<<cdiv(N_S, 128), 256>>>(Fs, Wsn, (const float*)nullptr,
                                         sbuf, 128, (float*)nullptr, 0, N_S, 16);

    // 4. UE aggregation via CSR
    hist_kernel<<<cdiv(E_UE, 256), 256>>>(ei_ue_dst, E_UE, cnt_ue);
    scan_excl<<<1, 1024>>>(cnt_ue, off, N_E);
    copy_int<<<cdiv(N_E, 256), 256>>>(off, wp, N_E);
    bucket_kernel<<<cdiv(E_UE, 256), 256>>>(ei_ue_src, ei_ue_dst, E_UE, wp, sorted);
    ue_agg<<<cdiv(N_E * 32, 256), 256>>>(ubuf, sorted, off, N_E, X);

    // 5. SE aggregation via atomics
    se_agg<<<cdiv(E_SE * 32, 256), 256>>>(sbuf, ei_se_src, ei_se_dst, E_SE, X, cnt_se);
    norm_se<<<cdiv(N_E * 128, 256), 256>>>(X, cnt_se, N_E);

    // 6. fused SAGE combine: email_h = lrelu(0.5*(out_se+out_ue)) -> C[:,0:128]
    sgemm128<2><<<cdiv(N_E, 128), 256>>>(X, Wc, bc, C, 256, (float*)nullptr, 0, N_E, 384);

    // 7. BatchNorm
    bn_stats<<<256, 256>>>(C, N_E, sums, sumsq);
    bn_finalize<<<1, 256>>>(sums, sumsq, bn_gamma, bn_beta, scale, shift, 1.0f / (float)N_E);

    // 8. classifier KAN
    classifier<<<cdiv(N_E * 32, 256), 256>>>(C, scale, shift, cls_base_w, cls_spline_w, out, N_E);
}

// round 4
// speedup vs baseline: 1.0153x; 1.0153x over previous
#include <cuda_runtime.h>
#include <math.h>
#include <stdint.h>

// ---------------------------------------------------------------------------
// Problem constants
// ---------------------------------------------------------------------------
#define NE_MAX 30000
#define NU_MAX 200000
#define NS_MAX 20000
#define EUE_MAX 1000000

// ---------------------------------------------------------------------------
// Device scratch
// ---------------------------------------------------------------------------
__device__ __align__(256) float g_Wu[128 * 96];
__device__ __align__(256) float g_Wsn[128 * 32];
__device__ __align__(256) float g_Wc[128 * 384];
__device__ float g_bc[128];
__device__ __align__(256) float g_Fu[(size_t)NU_MAX * 96];
__device__ __align__(256) float g_Fs[(size_t)NS_MAX * 32];
__device__ __align__(256) float g_u[(size_t)NU_MAX * 128];
__device__ __align__(256) float g_s[(size_t)NS_MAX * 128];
__device__ __align__(256) float g_X[(size_t)NE_MAX * 384]; // [agg_se | agg_ue | e]
__device__ __align__(256) float g_C[(size_t)NE_MAX * 256]; // [email_h | e]
__device__ int g_cnt_se[NE_MAX];
__device__ int g_cnt_ue[NE_MAX];
__device__ int g_off[NE_MAX + 1];
__device__ int g_wp[NE_MAX];
__device__ int g_sorted[EUE_MAX];
__device__ float g_sums[256];
__device__ float g_sumsq[256];
__device__ float g_scale[256];
__device__ float g_shift[256];

// ---------------------------------------------------------------------------
// tf32 conversion + hi/lo split (3xTF32 scheme)
// ---------------------------------------------------------------------------
__device__ __forceinline__ uint32_t f2tf(float f) {
    uint32_t r;
    asm("cvt.rna.tf32.f32 %0, %1;" : "=r"(r) : "f"(f));
    return r;
}

__device__ __forceinline__ void split_tf(float x, uint32_t& hi, uint32_t& lo) {
    hi = f2tf(x);
    lo = f2tf(x - __uint_as_float(hi));
}

__device__ __forceinline__ void mma8(float* c, const uint32_t* a, uint32_t b0, uint32_t b1) {
    asm volatile(
        "mma.sync.aligned.m16n8k8.row.col.f32.tf32.tf32.f32 "
        "{%0,%1,%2,%3}, {%4,%5,%6,%7}, {%8,%9}, {%0,%1,%2,%3};"
        : "+f"(c[0]), "+f"(c[1]), "+f"(c[2]), "+f"(c[3])
        : "r"(a[0]), "r"(a[1]), "r"(a[2]), "r"(a[3]), "r"(b0), "r"(b1));
}

// ---------------------------------------------------------------------------
// 3xTF32 mma.sync GEMM: C[M,128] = act(A[M,K] @ B[128,K]^T + bias)
// A row-major (lda), B row-major [128][ldb], K % 16 == 0.
// 128x128 tile/CTA, 256 threads, 8 warps (4 in M x 2 in N), warp tile 32x64.
// BK=16, double-buffered hi/lo SMEM (dynamic, 80KB), stride-20 padding.
// ---------------------------------------------------------------------------
#define SMS 20        // smem row stride in words
#define PBUF (128 * SMS)

template <int ACT, bool DUAL>  // ACT: 0=none 1=tanh 2=lrelu
__global__ void __launch_bounds__(256) mma_gemm(
    const float* __restrict__ A, int lda,
    const float* __restrict__ B, int ldb,
    const float* __restrict__ bias,
    float* __restrict__ Cp, int ldc,
    float* __restrict__ C2, int ldc2,
    int M, int K) {
    extern __shared__ uint32_t dyn[];
    uint32_t* Ah = dyn;                // [2][PBUF]
    uint32_t* Al = dyn + 2 * PBUF;
    uint32_t* Bh = dyn + 4 * PBUF;
    uint32_t* Bl = dyn + 6 * PBUF;

    int tid = threadIdx.x;
    int w = tid >> 5;
    int lane = tid & 31;
    int g = lane >> 2;   // 0..7
    int t4 = lane & 3;   // 0..3
    int wm = w & 3;      // warp M (4)
    int wn = w >> 2;     // warp N (2)

    int bm = blockIdx.x * 128;
    int rowsA = M - bm;
    if (rowsA > 128) rowsA = 128;
    int nch = K >> 4;

    float acc[2][8][4];
#pragma unroll
    for (int mt = 0; mt < 2; mt++)
#pragma unroll
        for (int nt = 0; nt < 8; nt++)
#pragma unroll
            for (int q = 0; q < 4; q++) acc[mt][nt][q] = 0.0f;

    int lrow = tid >> 1;       // 0..127
    int lq = (tid & 1) * 2;    // float4 index 0 or 2

    // prologue: chunk 0 -> buffer 0
    {
        const float* Ap = A + (size_t)bm * lda;
        const float* Bp = B;
#pragma unroll
        for (int i = 0; i < 2; i++) {
            int c4 = lq + i;
            float4 av = make_float4(0.f, 0.f, 0.f, 0.f);
            if (lrow < rowsA) av = *(const float4*)(Ap + (size_t)lrow * lda + c4 * 4);
            uint32_t* dh = &Ah[lrow * SMS + c4 * 4];
            uint32_t* dl = &Al[lrow * SMS + c4 * 4];
            split_tf(av.x, dh[0], dl[0]); split_tf(av.y, dh[1], dl[1]);
            split_tf(av.z, dh[2], dl[2]); split_tf(av.w, dh[3], dl[3]);
            float4 bv = *(const float4*)(Bp + (size_t)lrow * ldb + c4 * 4);
            uint32_t* eh = &Bh[lrow * SMS + c4 * 4];
            uint32_t* el = &Bl[lrow * SMS + c4 * 4];
            split_tf(bv.x, eh[0], el[0]); split_tf(bv.y, eh[1], el[1]);
            split_tf(bv.z, eh[2], el[2]); split_tf(bv.w, el[3] = 0, el[3]), split_tf(bv.w, eh[3], el[3]);
        }
    }
    __syncthreads();

    for (int c = 0; c < nch; c++) {
        int cur = c & 1;
        int nxt = cur ^ 1;
        float4 ga[2], gb[2];
        bool have_next = (c + 1 < nch);
        if (have_next) {
            const float* Ap = A + (size_t)bm * lda + (size_t)(c + 1) * 16;
            const float* Bp = B + (size_t)(c + 1) * 16;
#pragma unroll
            for (int i = 0; i < 2; i++) {
                int c4 = lq + i;
                ga[i] = make_float4(0.f, 0.f, 0.f, 0.f);
                if (lrow < rowsA) ga[i] = *(const float4*)(Ap + (size_t)lrow * lda + c4 * 4);
                gb[i] = *(const float4*)(Bp + (size_t)lrow * ldb + c4 * 4);
            }
        }

        const uint32_t* Abh = Ah + cur * PBUF;
        const uint32_t* Abl = Al + cur * PBUF;
        const uint32_t* Bbh = Bh + cur * PBUF;
        const uint32_t* Bbl = Bl + cur * PBUF;
#pragma unroll
        for (int ks = 0; ks < 16; ks += 8) {
            uint32_t ah[2][4], al[2][4];
#pragma unroll
            for (int mt = 0; mt < 2; mt++) {
                int r = wm * 32 + mt * 16 + g;
                const uint32_t* ph = Abh + r * SMS + ks + t4;
                ah[mt][0] = ph[0];
                ah[mt][1] = ph[8 * SMS];
                ah[mt][2] = ph[4];
                ah[mt][3] = ph[8 * SMS + 4];
                const uint32_t* pl = Abl + r * SMS + ks + t4;
                al[mt][0] = pl[0];
                al[mt][1] = pl[8 * SMS];
                al[mt][2] = pl[4];
                al[mt][3] = pl[8 * SMS + 4];
            }
#pragma unroll
            for (int nt = 0; nt < 8; nt++) {
                int n = wn * 64 + nt * 8 + g;
                const uint32_t* ph = Bbh + n * SMS + ks + t4;
                uint32_t bh0 = ph[0];
                uint32_t bh1 = ph[4];
                const uint32_t* pl = Bbl + n * SMS + ks + t4;
                uint32_t bl0 = pl[0];
                uint32_t bl1 = pl[4];
#pragma unroll
                for (int mt = 0; mt < 2; mt++) {
                    mma8(acc[mt][nt], al[mt], bh0, bh1);  // lo*hi
                    mma8(acc[mt][nt], ah[mt], bl0, bl1);  // hi*lo
                    mma8(acc[mt][nt], ah[mt], bh0, bh1);  // hi*hi
                }
            }
        }

        if (have_next) {
            uint32_t* Anh = Ah + nxt * PBUF;
            uint32_t* Anl = Al + nxt * PBUF;
            uint32_t* Bnh = Bh + nxt * PBUF;
            uint32_t* Bnl = Bl + nxt * PBUF;
#pragma unroll
            for (int i = 0; i < 2; i++) {
                int c4 = lq + i;
                uint32_t* dh = &Anh[lrow * SMS + c4 * 4];
                uint32_t* dl = &Anl[lrow * SMS + c4 * 4];
                split_tf(ga[i].x, dh[0], dl[0]); split_tf(ga[i].y, dh[1], dl[1]);
                split_tf(ga[i].z, dh[2], dl[2]); split_tf(ga[i].w, dh[3], dl[3]);
                uint32_t* eh = &Bnh[lrow * SMS + c4 * 4];
                uint32_t* el = &Bnl[lrow * SMS + c4 * 4];
                split_tf(gb[i].x, eh[0], el[0]); split_tf(gb[i].y, eh[1], el[1]);
                split_tf(gb[i].z, eh[2], el[2]); split_tf(gb[i].w, eh[3], el[3]);
            }
        }
        __syncthreads();
    }

    // epilogue
#pragma unroll
    for (int mt = 0; mt < 2; mt++) {
#pragma unroll
        for (int half = 0; half < 2; half++) {
            int r = bm + wm * 32 + mt * 16 + g + half * 8;
            if (r >= M) continue;
#pragma unroll
            for (int nt = 0; nt < 8; nt++) {
                int cc = wn * 64 + nt * 8 + t4 * 2;
                float vx = acc[mt][nt][half * 2 + 0];
                float vy = acc[mt][nt][half * 2 + 1];
                if (bias) {
                    vx += __ldg(&bias[cc + 0]);
                    vy += __ldg(&bias[cc + 1]);
                }
                if (ACT == 1) {
                    vx = tanhf(vx);
                    vy = tanhf(vy);
                } else if (ACT == 2) {
                    vx = vx >= 0.f ? vx : 0.2f * vx;
                    vy = vy >= 0.f ? vy : 0.2f * vy;
                }
                float2 v2 = make_float2(vx, vy);
                *(float2*)(Cp + (size_t)r * ldc + cc) = v2;
                if (DUAL) *(float2*)(C2 + (size_t)r * ldc2 + cc) = v2;
            }
        }
    }
}

// ---------------------------------------------------------------------------
// B-spline helpers
// ---------------------------------------------------------------------------
__device__ __forceinline__ float gknot(int i) {
    return (float)(i - 3) * 0.4f - 1.0f;
}

__device__ __forceinline__ void bspline8(float x, float* out) {
    float b[11];
#pragma unroll
    for (int i = 0; i < 11; i++) {
        b[i] = (x >= gknot(i) && x < gknot(i + 1)) ? 1.0f : 0.0f;
    }
#pragma unroll
    for (int j = 1; j <= 3; j++) {
#pragma unroll
        for (int i = 0; i <= 10 - j; i++) {
            float d1 = gknot(i + j) - gknot(i);
            float d2 = gknot(i + j + 1) - gknot(i + 1);
            b[i] = (x - gknot(i)) / d1 * b[i] + (gknot(i + j + 1) - x) / d2 * b[i + 1];
        }
    }
#pragma unroll
    for (int i = 0; i < 8; i++) out[i] = b[i];
}

__device__ __forceinline__ float silu(float x) {
    return x / (1.0f + expf(-x));
}

// ---------------------------------------------------------------------------
// Weight prep
// ---------------------------------------------------------------------------
__global__ void prep_url_w(const float* __restrict__ bw, const float* __restrict__ sw,
                           float* __restrict__ W) {
    int idx = blockIdx.x * blockDim.x + threadIdx.x;
    if (idx < 128 * 96) {
        int o = idx / 96, j = idx % 96;
        float v = 0.0f;
        if (j < 8) v = bw[o * 8 + j];
        else if (j < 72) v = sw[o * 64 + (j - 8)];
        W[idx] = v;
    }
}

__global__ void prep_snd_w(const float* __restrict__ bw, const float* __restrict__ sw,
                           float* __restrict__ W) {
    int idx = blockIdx.x * blockDim.x + threadIdx.x;
    if (idx < 128 * 32) {
        int o = idx / 32, j = idx % 32;
        float v = 0.0f;
        if (j < 1) v = bw[o];
        else if (j < 9) v = sw[o * 8 + (j - 1)];
        W[idx] = v;
    }
}

__global__ void prep_comb_w(const float* __restrict__ wlse, const float* __restrict__ wlue,
                            const float* __restrict__ wrse, const float* __restrict__ wrue,
                            const float* __restrict__ blse, const float* __restrict__ blue,
                            float* __restrict__ W, float* __restrict__ bc) {
    int idx = blockIdx.x * blockDim.x + threadIdx.x;
    if (idx < 128 * 384) {
        int o = idx / 384, k = idx % 384;
        float v;
        if (k < 128) v = wlse[o * 128 + k];
        else if (k < 256) v = wlue[o * 128 + (k - 128)];
        else v = wrse[o * 128 + (k - 256)] + wrue[o * 128 + (k - 256)];
        W[idx] = 0.5f * v;
    }
    if (idx < 128) bc[idx] = 0.5f * (blse[idx] + blue[idx]);
}

// ---------------------------------------------------------------------------
// KAN feature construction
// ---------------------------------------------------------------------------
__global__ void feat_url(const float* __restrict__ x, float* __restrict__ F, int n) {
    int gid = blockIdx.x * blockDim.x + threadIdx.x;
    if (gid < n * 8) {
        int nd = gid / 8, i = gid % 8;
        float v = x[gid];
        float* f = F + (size_t)nd * 96;
        f[i] = silu(v);
        float bs[8];
        bspline8(v, bs);
#pragma unroll
        for (int b = 0; b < 8; b++) f[8 + i * 8 + b] = bs[b];
        if (i == 0) {
#pragma unroll
            for (int j = 72; j < 96; j++) f[j] = 0.0f;
        }
    }
}

__global__ void feat_snd(const float* __restrict__ x, float* __restrict__ F, int n) {
    int gid = blockIdx.x * blockDim.x + threadIdx.x;
    if (gid < n) {
        float v = x[gid];
        float* f = F + (size_t)gid * 32;
        f[0] = silu(v);
        float bs[8];
        bspline8(v, bs);
#pragma unroll
        for (int b = 0; b < 8; b++) f[1 + b] = bs[b];
#pragma unroll
        for (int j = 9; j < 32; j++) f[j] = 0.0f;
    }
}

// ---------------------------------------------------------------------------
// SE aggregation: atomics (30k edges)
// ---------------------------------------------------------------------------
__global__ void zero_X_se(float* __restrict__ X, int n) {
    int idx = blockIdx.x * blockDim.x + threadIdx.x;
    int tot = n * 128;
    if (idx < tot) {
        int r = idx >> 7, c = idx & 127;
        X[(size_t)r * 384 + c] = 0.0f;
    }
}

__global__ void se_agg(const float* __restrict__ sfeat, const int* __restrict__ src,
                       const int* __restrict__ dst, int E, float* __restrict__ X,
                       int* __restrict__ cnt) {
    int w = (blockIdx.x * blockDim.x + threadIdx.x) >> 5;
    int lane = threadIdx.x & 31;
    int nw = (gridDim.x * blockDim.x) >> 5;
    for (int e = w; e < E; e += nw) {
        int sid = src[e];
        int did = dst[e];
#pragma unroll
        for (int q = 0; q < 4; q++) {
            int c = q * 32 + lane;
            float v = sfeat[(size_t)sid * 128 + c];
            atomicAdd(&X[(size_t)did * 384 + c], v);
        }
        if (lane == 0) atomicAdd(&cnt[did], 1);
    }
}

__global__ void norm_se(float* __restrict__ X, const int* __restrict__ cnt, int n) {
    int idx = blockIdx.x * blockDim.x + threadIdx.x;
    int tot = n * 128;
    if (idx < tot) {
        int r = idx >> 7, c = idx & 127;
        int k = cnt[r];
        X[(size_t)r * 384 + c] *= 1.0f / (float)(k > 0 ? k : 1);
    }
}

// ---------------------------------------------------------------------------
// UE aggregation: CSR bucketing
// ---------------------------------------------------------------------------
__global__ void hist_kernel(const int* __restrict__ dst, int E, int* __restrict__ cnt) {
    int gid = blockIdx.x * blockDim.x + threadIdx.x;
    if (gid < E) atomicAdd(&cnt[dst[gid]], 1);
}

__global__ void scan_excl(const int* __restrict__ in, int* __restrict__ out, int n) {
    __shared__ int sm[1024];
    __shared__ int s_carry;
    if (threadIdx.x == 0) s_carry = 0;
    __syncthreads();
    for (int base = 0; base < n; base += 1024) {
        int i = base + threadIdx.x;
        int v = (i < n) ? in[i] : 0;
        sm[threadIdx.x] = v;
        __syncthreads();
        for (int d = 1; d < 1024; d <<= 1) {
            int t = (threadIdx.x >= d) ? sm[threadIdx.x - d] : 0;
            __syncthreads();
            sm[threadIdx.x] += t;
            __syncthreads();
        }
        int incl = sm[threadIdx.x];
        int carry = s_carry;
        if (i < n) out[i] = carry + incl - v;
        __syncthreads();
        if (threadIdx.x == 0) s_carry = carry + sm[1023];
        __syncthreads();
    }
    if (threadIdx.x == 0) out[n] = s_carry;
}

__global__ void copy_int(const int* __restrict__ a, int* __restrict__ b, int n) {
    int gid = blockIdx.x * blockDim.x + threadIdx.x;
    if (gid < n) b[gid] = a[gid];
}

__global__ void bucket_kernel(const int* __restrict__ src, const int* __restrict__ dst,
                              int E, int* __restrict__ wp, int* __restrict__ sorted) {
    int gid = blockIdx.x * blockDim.x + threadIdx.x;
    if (gid < E) {
        int p = atomicAdd(&wp[dst[gid]], 1);
        sorted[p] = src[gid];
    }
}

__global__ void ue_agg(const float* __restrict__ u, const int* __restrict__ sorted,
                       const int* __restrict__ off, int ndst, float* __restrict__ X) {
    int w = (blockIdx.x * blockDim.x + threadIdx.x) >> 5;
    int lane = threadIdx.x & 31;
    int nw = (gridDim.x * blockDim.x) >> 5;
    for (int d = w; d < ndst; d += nw) {
        int a = off[d], b = off[d + 1];
        float4 acc = make_float4(0.f, 0.f, 0.f, 0.f);
        for (int e = a; e < b; e++) {
            int sid = sorted[e];
            float4 v = *(const float4*)(u + (size_t)sid * 128 + lane * 4);
            acc.x += v.x; acc.y += v.y; acc.z += v.z; acc.w += v.w;
        }
        float inv = 1.0f / (float)((b - a) > 0 ? (b - a) : 1);
        float4 o4 = make_float4(acc.x * inv, acc.y * inv, acc.z * inv, acc.w * inv);
        *(float4*)(X + (size_t)d * 384 + 128 + lane * 4) = o4;
    }
}

// ---------------------------------------------------------------------------
// BatchNorm
// ---------------------------------------------------------------------------
__global__ void bn_stats(const float* __restrict__ C, int n,
                         float* __restrict__ sums, float* __restrict__ sumsq) {
    int c = threadIdx.x;
    float s = 0.f, q = 0.f;
    for (int r = blockIdx.x; r < n; r += gridDim.x) {
        float v = C[(size_t)r * 256 + c];
        s += v;
        q += v * v;
    }
    atomicAdd(&sums[c], s);
    atomicAdd(&sumsq[c], q);
}

__global__ void bn_finalize(const float* __restrict__ sums, const float* __restrict__ sumsq,
                            const float* __restrict__ gamma, const float* __restrict__ beta,
                            float* __restrict__ scale, float* __restrict__ shift, float invn) {
    int c = threadIdx.x;
    float m = sums[c] * invn;
    float var = sumsq[c] * invn - m * m;
    float sc = gamma[c] / sqrtf(var + 1e-5f);
    scale[c] = sc;
    shift[c] = beta[c] - m * sc;
}

// ---------------------------------------------------------------------------
// Classifier KAN
// ---------------------------------------------------------------------------
__global__ void classifier(const float* __restrict__ C, const float* __restrict__ scale,
                           const float* __restrict__ shift, const float* __restrict__ cb,
                           const float* __restrict__ cs, float* __restrict__ out, int n) {
    int w = (blockIdx.x * blockDim.x + threadIdx.x) >> 5;
    int lane = threadIdx.x & 31;
    int nw = (gridDim.x * blockDim.x) >> 5;
    for (int r = w; r < n; r += nw) {
        float a0 = 0.f, a1 = 0.f;
#pragma unroll
        for (int q = 0; q < 8; q++) {
            int i = q * 32 + lane;
            float x = C[(size_t)r * 256 + i];
            x = x * scale[i] + shift[i];
            float sl = silu(x);
            float bs[8];
            bspline8(x, bs);
            a0 += sl * __ldg(&cb[i]);
            a1 += sl * __ldg(&cb[256 + i]);
            const float* w0 = cs + i * 8;
            const float* w1 = cs + 2048 + i * 8;
#pragma unroll
            for (int b = 0; b < 8; b++) {
                a0 += bs[b] * __ldg(&w0[b]);
                a1 += bs[b] * __ldg(&w1[b]);
            }
        }
#pragma unroll
        for (int sft = 16; sft > 0; sft >>= 1) {
            a0 += __shfl_down_sync(0xFFFFFFFFu, a0, sft);
            a1 += __shfl_down_sync(0xFFFFFFFFu, a1, sft);
        }
        if (lane == 0) {
            out[(size_t)r * 2 + 0] = a0;
            out[(size_t)r * 2 + 1] = a1;
        }
    }
}

// ---------------------------------------------------------------------------
// Launch
// ---------------------------------------------------------------------------
static inline unsigned cdiv(unsigned a, unsigned b) { return (a + b - 1) / b; }

extern "C" void kernel_launch(void* const* d_in, const int* in_sizes, int n_in,
                              void* d_out, int out_size) {
    const float* email_x = (const float*)d_in[0];
    const float* url_x = (const float*)d_in[1];
    const float* sender_x = (const float*)d_in[2];
    const float* W_email = (const float*)d_in[3];
    const float* b_email = (const float*)d_in[4];
    const float* url_base_w = (const float*)d_in[5];
    const float* url_spline_w = (const float*)d_in[6];
    const float* snd_base_w = (const float*)d_in[7];
    const float* snd_spline_w = (const float*)d_in[8];
    const float* Wl_se = (const float*)d_in[9];
    const float* bl_se = (const float*)d_in[10];
    const float* Wr_se = (const float*)d_in[11];
    const float* Wl_ue = (const float*)d_in[15];
    const float* bl_ue = (const float*)d_in[16];
    const float* Wr_ue = (const float*)d_in[17];
    const float* bn_gamma = (const float*)d_in[18];
    const float* bn_beta = (const float*)d_in[19];
    const float* cls_base_w = (const float*)d_in[20];
    const float* cls_spline_w = (const float*)d_in[21];
    const int* ei_se_src = (const int*)d_in[22];
    const int* ei_se_dst = (const int*)d_in[23];
    const int* ei_ue_src = (const int*)d_in[26];
    const int* ei_ue_dst = (const int*)d_in[27];

    int N_E = in_sizes[0] / 768;
    int N_U = in_sizes[1] / 8;
    int N_S = in_sizes[2];
    int E_SE = in_sizes[22];
    int E_UE = in_sizes[26];

    float* out = (float*)d_out;

    float *Wu, *Wsn, *Wc, *bc, *Fu, *Fs, *ubuf, *sbuf, *X, *C;
    float *sums, *sumsq, *scale, *shift;
    int *cnt_se, *cnt_ue, *off, *wp, *sorted;
    cudaGetSymbolAddress((void**)&Wu, g_Wu);
    cudaGetSymbolAddress((void**)&Wsn, g_Wsn);
    cudaGetSymbolAddress((void**)&Wc, g_Wc);
    cudaGetSymbolAddress((void**)&bc, g_bc);
    cudaGetSymbolAddress((void**)&Fu, g_Fu);
    cudaGetSymbolAddress((void**)&Fs, g_Fs);
    cudaGetSymbolAddress((void**)&ubuf, g_u);
    cudaGetSymbolAddress((void**)&sbuf, g_s);
    cudaGetSymbolAddress((void**)&X, g_X);
    cudaGetSymbolAddress((void**)&C, g_C);
    cudaGetSymbolAddress((void**)&sums, g_sums);
    cudaGetSymbolAddress((void**)&sumsq, g_sumsq);
    cudaGetSymbolAddress((void**)&scale, g_scale);
    cudaGetSymbolAddress((void**)&shift, g_shift);
    cudaGetSymbolAddress((void**)&cnt_se, g_cnt_se);
    cudaGetSymbolAddress((void**)&cnt_ue, g_cnt_ue);
    cudaGetSymbolAddress((void**)&off, g_off);
    cudaGetSymbolAddress((void**)&wp, g_wp);
    cudaGetSymbolAddress((void**)&sorted, g_sorted);

    const int GSMEM = 8 * PBUF * 4;  // 81920 bytes
    cudaFuncSetAttribute(mma_gemm<1, true>, cudaFuncAttributeMaxDynamicSharedMemorySize, GSMEM);
    cudaFuncSetAttribute(mma_gemm<1, false>, cudaFuncAttributeMaxDynamicSharedMemorySize, GSMEM);
    cudaFuncSetAttribute(mma_gemm<2, false>, cudaFuncAttributeMaxDynamicSharedMemorySize, GSMEM);

    // 0. zero accumulators
    cudaMemsetAsync(cnt_se, 0, (size_t)N_E * sizeof(int), 0);
    cudaMemsetAsync(cnt_ue, 0, (size_t)N_E * sizeof(int), 0);
    cudaMemsetAsync(sums, 0, 256 * sizeof(float), 0);
    cudaMemsetAsync(sumsq, 0, 256 * sizeof(float), 0);
    zero_X_se<<<cdiv(N_E * 128, 256), 256>>>(X, N_E);

    // 1. weight prep
    prep_url_w<<<cdiv(128 * 96, 256), 256>>>(url_base_w, url_spline_w, Wu);
    prep_snd_w<<<cdiv(128 * 32, 256), 256>>>(snd_base_w, snd_spline_w, Wsn);
    prep_comb_w<<<cdiv(128 * 384, 256), 256>>>(Wl_se, Wl_ue, Wr_se, Wr_ue, bl_se, bl_ue, Wc, bc);

    // 2. KAN features
    feat_url<<<cdiv(N_U * 8, 256), 256>>>(url_x, Fu, N_U);
    feat_snd<<<cdiv(N_S, 256), 256>>>(sender_x, Fs, N_S);

    // 3. embeddings via 3xTF32 mma GEMMs
    mma_gemm<1, true><<<cdiv(N_E, 128), 256, GSMEM>>>(
        email_x, 768, W_email, 768, b_email, X + 256, 384, C + 128, 256, N_E, 768);
    mma_gemm<1, false><<<cdiv(N_U, 128), 256, GSMEM>>>(
        Fu, 96, Wu, 96, (const float*)nullptr, ubuf, 128, (float*)nullptr, 0, N_U, 96);
    mma_gemm<1, false><<<cdiv(N_S, 128), 256, GSMEM>>>(
        Fs, 32, Wsn, 32, (const float*)nullptr, sbuf, 128, (float*)nullptr, 0, N_S, 32);

    // 4. UE aggregation via CSR
    hist_kernel<<<cdiv(E_UE, 256), 256>>>(ei_ue_dst, E_UE, cnt_ue);
    scan_excl<<<1, 1024>>>(cnt_ue, off, N_E);
    copy_int<<<cdiv(N_E, 256), 256>>>(off, wp, N_E);
    bucket_kernel<<<cdiv(E_UE, 256), 256>>>(ei_ue_src, ei_ue_dst, E_UE, wp, sorted);
    ue_agg<<<cdiv(N_E * 32, 256), 256>>>(ubuf, sorted, off, N_E, X);

    // 5. SE aggregation via atomics
    se_agg<<<cdiv(E_SE * 32, 256), 256>>>(sbuf, ei_se_src, ei_se_dst, E_SE, X, cnt_se);
    norm_se<<<cdiv(N_E * 128, 256), 256>>>(X, cnt_se, N_E);

    // 6. fused SAGE combine -> C[:,0:128]
    mma_gemm<2, false><<<cdiv(N_E, 128), 256, GSMEM>>>(
        X, 384, Wc, 384, bc, C, 256, (float*)nullptr, 0, N_E, 384);

    // 7. BatchNorm
    bn_stats<<<256, 256>>>(C, N_E, sums, sumsq);
    bn_finalize<<<1, 256>>>(sums, sumsq, bn_gamma, bn_beta, scale, shift, 1.0f / (float)N_E);

    // 8. classifier KAN
    classifier<<<cdiv(N_E * 32, 256), 256>>>(C, scale, shift, cls_base_w, cls_spline_w, out, N_E);
}

// round 5
// speedup vs baseline: 1.0317x; 1.0162x over previous
#include <cuda_runtime.h>
#include <math.h>
#include <stdint.h>

// ---------------------------------------------------------------------------
// Problem constants
// ---------------------------------------------------------------------------
#define NE_MAX 30000
#define NU_MAX 200000
#define NS_MAX 20000
#define EUE_MAX 1000000

// ---------------------------------------------------------------------------
// Device scratch
// ---------------------------------------------------------------------------
__device__ __align__(256) float g_WeT[768 * 128];   // W_email k-major [768][128]
__device__ __align__(256) float g_Wu[72 * 128];     // url KAN weight k-major [72][128]
__device__ __align__(256) float g_Wsn[16 * 128];    // sender KAN weight k-major [16][128]
__device__ __align__(256) float g_Wc[384 * 128];    // combined SAGE weight k-major [384][128]
__device__ float g_bc[128];
__device__ __align__(256) float g_Fu[(size_t)NU_MAX * 72];
__device__ __align__(256) float g_Fs[(size_t)NS_MAX * 16];
__device__ __align__(256) float g_u[(size_t)NU_MAX * 128];
__device__ __align__(256) float g_s[(size_t)NS_MAX * 128];
__device__ __align__(256) float g_X[(size_t)NE_MAX * 384]; // [agg_se | agg_ue | e]
__device__ __align__(256) float g_C[(size_t)NE_MAX * 256]; // [email_h | e]
__device__ int g_cnt_se[NE_MAX];
__device__ int g_cnt_ue[NE_MAX];
__device__ int g_off[NE_MAX + 1];
__device__ int g_wp[NE_MAX];
__device__ int g_part[256];
__device__ int g_sorted[EUE_MAX];
__device__ float g_sums[256];
__device__ float g_sumsq[256];
__device__ float g_scale[256];
__device__ float g_shift[256];

// ---------------------------------------------------------------------------
// Packed fp32x2 helpers (sm_103a FFMA2 path)
// ---------------------------------------------------------------------------
__device__ __forceinline__ unsigned long long dup2(float x) {
    unsigned long long r;
    asm("mov.b64 %0, {%1, %1};" : "=l"(r) : "f"(x));
    return r;
}
__device__ __forceinline__ unsigned long long pack2(float x, float y) {
    unsigned long long r;
    asm("mov.b64 %0, {%1, %2};" : "=l"(r) : "f"(x), "f"(y));
    return r;
}
__device__ __forceinline__ float2 unpack2(unsigned long long v) {
    float2 f;
    asm("mov.b64 {%0, %1}, %2;" : "=f"(f.x), "=f"(f.y) : "l"(v));
    return f;
}
__device__ __forceinline__ unsigned long long fma2(unsigned long long a, unsigned long long b,
                                                   unsigned long long c) {
    unsigned long long d;
    asm("fma.rn.f32x2 %0, %1, %2, %3;" : "=l"(d) : "l"(a), "l"(b), "l"(c));
    return d;
}

// ---------------------------------------------------------------------------
// SIMT fp32x2 SGEMM: C[M,128] = act(A[M,K] @ Bk[K][128] + bias)
// A row-major (lda); Bk k-major [K][128]. K % 8 == 0.
// 128x128 tile/CTA, 256 threads, 8x8 per thread (4 f32x2 pairs per row),
// BK=8, double-buffered SMEM (stride 132).
// ---------------------------------------------------------------------------
template <int ACT, bool DUAL>  // ACT: 0=none 1=tanh 2=lrelu
__global__ void __launch_bounds__(256) sgemm2(
    const float* __restrict__ A, int lda,
    const float* __restrict__ Bk,
    const float* __restrict__ bias,
    float* __restrict__ Cp, int ldc,
    float* __restrict__ C2, int ldc2,
    int M, int K) {
    __shared__ float As[2][8][132];
    __shared__ float Bs[2][8][132];

    int tid = threadIdx.x;
    int tx = tid % 16;
    int ty = tid / 16;

    int bm = blockIdx.x * 128;
    int rowsA = M - bm;
    if (rowsA > 128) rowsA = 128;
    int nch = K >> 3;

    unsigned long long acc[8][4];
#pragma unroll
    for (int i = 0; i < 8; i++)
#pragma unroll
        for (int j = 0; j < 4; j++) acc[i][j] = 0ull;

    int a_row = tid >> 1;        // 0..127
    int a_kq = (tid & 1) * 4;    // 0 or 4
    int b_k = tid >> 5;          // 0..7
    int b_col = (tid & 31) * 4;  // 0..124

    // prologue: chunk 0 -> buffer 0
    {
        float4 av = make_float4(0.f, 0.f, 0.f, 0.f);
        if (a_row < rowsA) av = *(const float4*)(A + (size_t)(bm + a_row) * lda + a_kq);
        As[0][a_kq + 0][a_row] = av.x;
        As[0][a_kq + 1][a_row] = av.y;
        As[0][a_kq + 2][a_row] = av.z;
        As[0][a_kq + 3][a_row] = av.w;
        float4 bv = *(const float4*)(Bk + (size_t)b_k * 128 + b_col);
        *(float4*)&Bs[0][b_k][b_col] = bv;
    }
    __syncthreads();

    for (int c = 0; c < nch; c++) {
        int cur = c & 1;
        int nxt = cur ^ 1;
        bool have_next = (c + 1 < nch);
        float4 ga = make_float4(0.f, 0.f, 0.f, 0.f);
        float4 gb = make_float4(0.f, 0.f, 0.f, 0.f);
        if (have_next) {
            int k0 = (c + 1) * 8;
            if (a_row < rowsA) ga = *(const float4*)(A + (size_t)(bm + a_row) * lda + k0 + a_kq);
            gb = *(const float4*)(Bk + (size_t)(k0 + b_k) * 128 + b_col);
        }

#pragma unroll
        for (int k = 0; k < 8; k++) {
            float4 a0 = *(const float4*)&As[cur][k][ty * 8];
            float4 a1 = *(const float4*)&As[cur][k][ty * 8 + 4];
            float4 b0 = *(const float4*)&Bs[cur][k][tx * 8];
            float4 b1 = *(const float4*)&Bs[cur][k][tx * 8 + 4];
            unsigned long long bp0 = pack2(b0.x, b0.y);
            unsigned long long bp1 = pack2(b0.z, b0.w);
            unsigned long long bp2 = pack2(b1.x, b1.y);
            unsigned long long bp3 = pack2(b1.z, b1.w);
            float av8[8] = {a0.x, a0.y, a0.z, a0.w, a1.x, a1.y, a1.z, a1.w};
#pragma unroll
            for (int i = 0; i < 8; i++) {
                unsigned long long ad = dup2(av8[i]);
                acc[i][0] = fma2(ad, bp0, acc[i][0]);
                acc[i][1] = fma2(ad, bp1, acc[i][1]);
                acc[i][2] = fma2(ad, bp2, acc[i][2]);
                acc[i][3] = fma2(ad, bp3, acc[i][3]);
            }
        }

        if (have_next) {
            As[nxt][a_kq + 0][a_row] = ga.x;
            As[nxt][a_kq + 1][a_row] = ga.y;
            As[nxt][a_kq + 2][a_row] = ga.z;
            As[nxt][a_kq + 3][a_row] = ga.w;
            *(float4*)&Bs[nxt][b_k][b_col] = gb;
        }
        __syncthreads();
    }

    // epilogue
#pragma unroll
    for (int i = 0; i < 8; i++) {
        int r = bm + ty * 8 + i;
        if (r >= M) continue;
#pragma unroll
        for (int jp = 0; jp < 4; jp++) {
            int cc = tx * 8 + jp * 2;
            float2 v = unpack2(acc[i][jp]);
            if (bias) {
                v.x += __ldg(&bias[cc + 0]);
                v.y += __ldg(&bias[cc + 1]);
            }
            if (ACT == 1) {
                v.x = tanhf(v.x);
                v.y = tanhf(v.y);
            } else if (ACT == 2) {
                v.x = v.x >= 0.f ? v.x : 0.2f * v.x;
                v.y = v.y >= 0.f ? v.y : 0.2f * v.y;
            }
            *(float2*)(Cp + (size_t)r * ldc + cc) = v;
            if (DUAL) *(float2*)(C2 + (size_t)r * ldc2 + cc) = v;
        }
    }
}

// ---------------------------------------------------------------------------
// B-spline helpers
// ---------------------------------------------------------------------------
__device__ __forceinline__ float gknot(int i) {
    return (float)(i - 3) * 0.4f - 1.0f;
}

__device__ __forceinline__ void bspline8(float x, float* out) {
    float b[11];
#pragma unroll
    for (int i = 0; i < 11; i++) {
        b[i] = (x >= gknot(i) && x < gknot(i + 1)) ? 1.0f : 0.0f;
    }
#pragma unroll
    for (int j = 1; j <= 3; j++) {
#pragma unroll
        for (int i = 0; i <= 10 - j; i++) {
            float d1 = gknot(i + j) - gknot(i);
            float d2 = gknot(i + j + 1) - gknot(i + 1);
            b[i] = (x - gknot(i)) / d1 * b[i] + (gknot(i + j + 1) - x) / d2 * b[i + 1];
        }
    }
#pragma unroll
    for (int i = 0; i < 8; i++) out[i] = b[i];
}

__device__ __forceinline__ float silu(float x) {
    return x / (1.0f + expf(-x));
}

// ---------------------------------------------------------------------------
// Weight prep (k-major [K][128])
// ---------------------------------------------------------------------------
__global__ void prep_email_w(const float* __restrict__ W, float* __restrict__ Wt) {
    int idx = blockIdx.x * blockDim.x + threadIdx.x;
    if (idx < 768 * 128) {
        int k = idx / 128, o = idx % 128;
        Wt[idx] = W[o * 768 + k];
    }
}

__global__ void prep_url_w(const float* __restrict__ bw, const float* __restrict__ sw,
                           float* __restrict__ Wt) {
    int idx = blockIdx.x * blockDim.x + threadIdx.x;
    if (idx < 72 * 128) {
        int j = idx / 128, o = idx % 128;
        Wt[idx] = (j < 8) ? bw[o * 8 + j] : sw[o * 64 + (j - 8)];
    }
}

__global__ void prep_snd_w(const float* __restrict__ bw, const float* __restrict__ sw,
                           float* __restrict__ Wt) {
    int idx = blockIdx.x * blockDim.x + threadIdx.x;
    if (idx < 16 * 128) {
        int j = idx / 128, o = idx % 128;
        float v = 0.0f;
        if (j < 1) v = bw[o];
        else if (j < 9) v = sw[o * 8 + (j - 1)];
        Wt[idx] = v;
    }
}

__global__ void prep_comb_w(const float* __restrict__ wlse, const float* __restrict__ wlue,
                            const float* __restrict__ wrse, const float* __restrict__ wrue,
                            const float* __restrict__ blse, const float* __restrict__ blue,
                            float* __restrict__ Wt, float* __restrict__ bc) {
    int idx = blockIdx.x * blockDim.x + threadIdx.x;
    if (idx < 384 * 128) {
        int k = idx / 128, o = idx % 128;
        float v;
        if (k < 128) v = wlse[o * 128 + k];
        else if (k < 256) v = wlue[o * 128 + (k - 128)];
        else v = wrse[o * 128 + (k - 256)] + wrue[o * 128 + (k - 256)];
        Wt[idx] = 0.5f * v;
    }
    if (idx < 128) bc[idx] = 0.5f * (blse[idx] + blue[idx]);
}

// ---------------------------------------------------------------------------
// KAN feature construction
// ---------------------------------------------------------------------------
__global__ void feat_url(const float* __restrict__ x, float* __restrict__ F, int n) {
    int gid = blockIdx.x * blockDim.x + threadIdx.x;
    if (gid < n * 8) {
        int nd = gid / 8, i = gid % 8;
        float v = x[gid];
        float* f = F + (size_t)nd * 72;
        f[i] = silu(v);
        float bs[8];
        bspline8(v, bs);
#pragma unroll
        for (int b = 0; b < 8; b++) f[8 + i * 8 + b] = bs[b];
    }
}

__global__ void feat_snd(const float* __restrict__ x, float* __restrict__ F, int n) {
    int gid = blockIdx.x * blockDim.x + threadIdx.x;
    if (gid < n) {
        float v = x[gid];
        float* f = F + (size_t)gid * 16;
        f[0] = silu(v);
        float bs[8];
        bspline8(v, bs);
#pragma unroll
        for (int b = 0; b < 8; b++) f[1 + b] = bs[b];
#pragma unroll
        for (int j = 9; j < 16; j++) f[j] = 0.0f;
    }
}

// ---------------------------------------------------------------------------
// SE aggregation: atomics (30k edges)
// ---------------------------------------------------------------------------
__global__ void zero_X_se(float* __restrict__ X, int n) {
    int idx = blockIdx.x * blockDim.x + threadIdx.x;
    int tot = n * 128;
    if (idx < tot) {
        int r = idx >> 7, c = idx & 127;
        X[(size_t)r * 384 + c] = 0.0f;
    }
}

__global__ void se_agg(const float* __restrict__ sfeat, const int* __restrict__ src,
                       const int* __restrict__ dst, int E, float* __restrict__ X,
                       int* __restrict__ cnt) {
    int w = (blockIdx.x * blockDim.x + threadIdx.x) >> 5;
    int lane = threadIdx.x & 31;
    int nw = (gridDim.x * blockDim.x) >> 5;
    for (int e = w; e < E; e += nw) {
        int sid = src[e];
        int did = dst[e];
#pragma unroll
        for (int q = 0; q < 4; q++) {
            int c = q * 32 + lane;
            float v = sfeat[(size_t)sid * 128 + c];
            atomicAdd(&X[(size_t)did * 384 + c], v);
        }
        if (lane == 0) atomicAdd(&cnt[did], 1);
    }
}

__global__ void norm_se(float* __restrict__ X, const int* __restrict__ cnt, int n) {
    int idx = blockIdx.x * blockDim.x + threadIdx.x;
    int tot = n * 128;
    if (idx < tot) {
        int r = idx >> 7, c = idx & 127;
        int k = cnt[r];
        X[(size_t)r * 384 + c] *= 1.0f / (float)(k > 0 ? k : 1);
    }
}

// ---------------------------------------------------------------------------
// UE aggregation: CSR bucketing with fast 3-kernel scan
// ---------------------------------------------------------------------------
__global__ void hist_kernel(const int* __restrict__ dst, int E, int* __restrict__ cnt) {
    int gid = blockIdx.x * blockDim.x + threadIdx.x;
    if (gid < E) atomicAdd(&cnt[dst[gid]], 1);
}

__global__ void scan1(const int* __restrict__ in, int* __restrict__ chunk,
                      int* __restrict__ part, int n) {
    __shared__ int sm[256];
    int t = threadIdx.x;
    int i = blockIdx.x * 256 + t;
    int v = (i < n) ? in[i] : 0;
    sm[t] = v;
    __syncthreads();
#pragma unroll
    for (int d = 1; d < 256; d <<= 1) {
        int x = (t >= d) ? sm[t - d] : 0;
        __syncthreads();
        sm[t] += x;
        __syncthreads();
    }
    if (i < n) chunk[i] = sm[t] - v;
    if (t == 255) part[blockIdx.x] = sm[255];
}

__global__ void scan2(int* __restrict__ part, int nb) {
    __shared__ int sm[128];
    int t = threadIdx.x;
    int v = (t < nb) ? part[t] : 0;
    sm[t] = v;
    __syncthreads();
#pragma unroll
    for (int d = 1; d < 128; d <<= 1) {
        int x = (t >= d) ? sm[t - d] : 0;
        __syncthreads();
        sm[t] += x;
        __syncthreads();
    }
    if (t < nb) part[t] = sm[t] - v;
}

__global__ void scan3(const int* __restrict__ chunk, const int* __restrict__ part,
                      int* __restrict__ off, int* __restrict__ wp, int n, int E) {
    int i = blockIdx.x * blockDim.x + threadIdx.x;
    if (i < n) {
        int o = chunk[i] + part[i >> 8];
        off[i] = o;
        wp[i] = o;
    }
    if (i == 0) off[n] = E;
}

__global__ void bucket_kernel(const int* __restrict__ src, const int* __restrict__ dst,
                              int E, int* __restrict__ wp, int* __restrict__ sorted) {
    int gid = blockIdx.x * blockDim.x + threadIdx.x;
    if (gid < E) {
        int p = atomicAdd(&wp[dst[gid]], 1);
        sorted[p] = src[gid];
    }
}

__global__ void ue_agg(const float* __restrict__ u, const int* __restrict__ sorted,
                       const int* __restrict__ off, int ndst, float* __restrict__ X) {
    int w = (blockIdx.x * blockDim.x + threadIdx.x) >> 5;
    int lane = threadIdx.x & 31;
    int nw = (gridDim.x * blockDim.x) >> 5;
    for (int d = w; d < ndst; d += nw) {
        int a = off[d], b = off[d + 1];
        float4 ac0 = make_float4(0.f, 0.f, 0.f, 0.f);
        float4 ac1 = make_float4(0.f, 0.f, 0.f, 0.f);
        int e = a;
        for (; e + 2 <= b; e += 2) {
            int s0 = sorted[e];
            int s1 = sorted[e + 1];
            float4 v0 = *(const float4*)(u + (size_t)s0 * 128 + lane * 4);
            float4 v1 = *(const float4*)(u + (size_t)s1 * 128 + lane * 4);
            ac0.x += v0.x; ac0.y += v0.y; ac0.z += v0.z; ac0.w += v0.w;
            ac1.x += v1.x; ac1.y += v1.y; ac1.z += v1.z; ac1.w += v1.w;
        }
        if (e < b) {
            int s0 = sorted[e];
            float4 v0 = *(const float4*)(u + (size_t)s0 * 128 + lane * 4);
            ac0.x += v0.x; ac0.y += v0.y; ac0.z += v0.z; ac0.w += v0.w;
        }
        ac0.x += ac1.x; ac0.y += ac1.y; ac0.z += ac1.z; ac0.w += ac1.w;
        float inv = 1.0f / (float)((b - a) > 0 ? (b - a) : 1);
        float4 o4 = make_float4(ac0.x * inv, ac0.y * inv, ac0.z * inv, ac0.w * inv);
        *(float4*)(X + (size_t)d * 384 + 128 + lane * 4) = o4;
    }
}

// ---------------------------------------------------------------------------
// BatchNorm
// ---------------------------------------------------------------------------
__global__ void bn_stats(const float* __restrict__ C, int n,
                         float* __restrict__ sums, float* __restrict__ sumsq) {
    int c = threadIdx.x;
    float s = 0.f, q = 0.f;
    for (int r = blockIdx.x; r < n; r += gridDim.x) {
        float v = C[(size_t)r * 256 + c];
        s += v;
        q += v * v;
    }
    atomicAdd(&sums[c], s);
    atomicAdd(&sumsq[c], q);
}

__global__ void bn_finalize(const float* __restrict__ sums, const float* __restrict__ sumsq,
                            const float* __restrict__ gamma, const float* __restrict__ beta,
                            float* __restrict__ scale, float* __restrict__ shift, float invn) {
    int c = threadIdx.x;
    float m = sums[c] * invn;
    float var = sumsq[c] * invn - m * m;
    float sc = gamma[c] / sqrtf(var + 1e-5f);
    scale[c] = sc;
    shift[c] = beta[c] - m * sc;
}

// ---------------------------------------------------------------------------
// Classifier KAN
// ---------------------------------------------------------------------------
__global__ void classifier(const float* __restrict__ C, const float* __restrict__ scale,
                           const float* __restrict__ shift, const float* __restrict__ cb,
                           const float* __restrict__ cs, float* __restrict__ out, int n) {
    int w = (blockIdx.x * blockDim.x + threadIdx.x) >> 5;
    int lane = threadIdx.x & 31;
    int nw = (gridDim.x * blockDim.x) >> 5;
    for (int r = w; r < n; r += nw) {
        float a0 = 0.f, a1 = 0.f;
#pragma unroll
        for (int q = 0; q < 8; q++) {
            int i = q * 32 + lane;
            float x = C[(size_t)r * 256 + i];
            x = x * scale[i] + shift[i];
            float sl = silu(x);
            float bs[8];
            bspline8(x, bs);
            a0 += sl * __ldg(&cb[i]);
            a1 += sl * __ldg(&cb[256 + i]);
            const float* w0 = cs + i * 8;
            const float* w1 = cs + 2048 + i * 8;
#pragma unroll
            for (int b = 0; b < 8; b++) {
                a0 += bs[b] * __ldg(&w0[b]);
                a1 += bs[b] * __ldg(&w1[b]);
            }
        }
#pragma unroll
        for (int sft = 16; sft > 0; sft >>= 1) {
            a0 += __shfl_down_sync(0xFFFFFFFFu, a0, sft);
            a1 += __shfl_down_sync(0xFFFFFFFFu, a1, sft);
        }
        if (lane == 0) {
            out[(size_t)r * 2 + 0] = a0;
            out[(size_t)r * 2 + 1] = a1;
        }
    }
}

// ---------------------------------------------------------------------------
// Launch
// ---------------------------------------------------------------------------
static inline unsigned cdiv(unsigned a, unsigned b) { return (a + b - 1) / b; }

extern "C" void kernel_launch(void* const* d_in, const int* in_sizes, int n_in,
                              void* d_out, int out_size) {
    const float* email_x = (const float*)d_in[0];
    const float* url_x = (const float*)d_in[1];
    const float* sender_x = (const float*)d_in[2];
    const float* W_email = (const float*)d_in[3];
    const float* b_email = (const float*)d_in[4];
    const float* url_base_w = (const float*)d_in[5];
    const float* url_spline_w = (const float*)d_in[6];
    const float* snd_base_w = (const float*)d_in[7];
    const float* snd_spline_w = (const float*)d_in[8];
    const float* Wl_se = (const float*)d_in[9];
    const float* bl_se = (const float*)d_in[10];
    const float* Wr_se = (const float*)d_in[11];
    const float* Wl_ue = (const float*)d_in[15];
    const float* bl_ue = (const float*)d_in[16];
    const float* Wr_ue = (const float*)d_in[17];
    const float* bn_gamma = (const float*)d_in[18];
    const float* bn_beta = (const float*)d_in[19];
    const float* cls_base_w = (const float*)d_in[20];
    const float* cls_spline_w = (const float*)d_in[21];
    const int* ei_se_src = (const int*)d_in[22];
    const int* ei_se_dst = (const int*)d_in[23];
    const int* ei_ue_src = (const int*)d_in[26];
    const int* ei_ue_dst = (const int*)d_in[27];

    int N_E = in_sizes[0] / 768;
    int N_U = in_sizes[1] / 8;
    int N_S = in_sizes[2];
    int E_SE = in_sizes[22];
    int E_UE = in_sizes[26];

    float* out = (float*)d_out;

    float *WeT, *Wu, *Wsn, *Wc, *bc, *Fu, *Fs, *ubuf, *sbuf, *X, *C;
    float *sums, *sumsq, *scale, *shift;
    int *cnt_se, *cnt_ue, *off, *wp, *part, *sorted;
    cudaGetSymbolAddress((void**)&WeT, g_WeT);
    cudaGetSymbolAddress((void**)&Wu, g_Wu);
    cudaGetSymbolAddress((void**)&Wsn, g_Wsn);
    cudaGetSymbolAddress((void**)&Wc, g_Wc);
    cudaGetSymbolAddress((void**)&bc, g_bc);
    cudaGetSymbolAddress((void**)&Fu, g_Fu);
    cudaGetSymbolAddress((void**)&Fs, g_Fs);
    cudaGetSymbolAddress((void**)&ubuf, g_u);
    cudaGetSymbolAddress((void**)&sbuf, g_s);
    cudaGetSymbolAddress((void**)&X, g_X);
    cudaGetSymbolAddress((void**)&C, g_C);
    cudaGetSymbolAddress((void**)&sums, g_sums);
    cudaGetSymbolAddress((void**)&sumsq, g_sumsq);
    cudaGetSymbolAddress((void**)&scale, g_scale);
    cudaGetSymbolAddress((void**)&shift, g_shift);
    cudaGetSymbolAddress((void**)&cnt_se, g_cnt_se);
    cudaGetSymbolAddress((void**)&cnt_ue, g_cnt_ue);
    cudaGetSymbolAddress((void**)&off, g_off);
    cudaGetSymbolAddress((void**)&wp, g_wp);
    cudaGetSymbolAddress((void**)&part, g_part);
    cudaGetSymbolAddress((void**)&sorted, g_sorted);

    // launches 0-3: memsets
    cudaMemsetAsync(cnt_se, 0, (size_t)N_E * sizeof(int), 0);
    cudaMemsetAsync(cnt_ue, 0, (size_t)N_E * sizeof(int), 0);
    cudaMemsetAsync(sums, 0, 256 * sizeof(float), 0);
    cudaMemsetAsync(sumsq, 0, 256 * sizeof(float), 0);
    // 4
    zero_X_se<<<cdiv(N_E * 128, 256), 256>>>(X, N_E);
    // 5
    prep_comb_w<<<cdiv(384 * 128, 256), 256>>>(Wl_se, Wl_ue, Wr_se, Wr_ue, bl_se, bl_ue, Wc, bc);
    // 6
    prep_email_w<<<cdiv(768 * 128, 256), 256>>>(W_email, WeT);
    // 7: email GEMM  (profiled slot)
    sgemm2<1, true><<<cdiv(N_E, 128), 256>>>(
        email_x, 768, WeT, b_email, X + 256, 384, C + 128, 256, N_E, 768);
    // 8-10: url path prep
    prep_url_w<<<cdiv(72 * 128, 256), 256>>>(url_base_w, url_spline_w, Wu);
    feat_url<<<cdiv(N_U * 8, 256), 256>>>(url_x, Fu, N_U);
    sgemm2<1, false><<<cdiv(N_U, 128), 256>>>(
        Fu, 72, Wu, (const float*)nullptr, ubuf, 128, (float*)nullptr, 0, N_U, 72);
    // 11-13: sender path
    prep_snd_w<<<cdiv(16 * 128, 256), 256>>>(snd_base_w, snd_spline_w, Wsn);
    feat_snd<<<cdiv(N_S, 256), 256>>>(sender_x, Fs, N_S);
    sgemm2<1, false><<<cdiv(N_S, 128), 256>>>(
        Fs, 16, Wsn, (const float*)nullptr, sbuf, 128, (float*)nullptr, 0, N_S, 16);
    // 14-18: UE CSR + aggregate
    hist_kernel<<<cdiv(E_UE, 256), 256>>>(ei_ue_dst, E_UE, cnt_ue);
    int nb = cdiv(N_E, 256);
    scan1<<<nb, 256>>>(cnt_ue, wp, part, N_E);
    scan2<<<1, 128>>>(part, nb);
    scan3<<<cdiv(N_E, 256), 256>>>(wp, part, off, wp, N_E, E_UE);
    bucket_kernel<<<cdiv(E_UE, 256), 256>>>(ei_ue_src, ei_ue_dst, E_UE, wp, sorted);
    ue_agg<<<cdiv(N_E * 32, 256), 256>>>(ubuf, sorted, off, N_E, X);
    // 19-20: SE aggregate
    se_agg<<<cdiv(E_SE * 32, 256), 256>>>(sbuf, ei_se_src, ei_se_dst, E_SE, X, cnt_se);
    norm_se<<<cdiv(N_E * 128, 256), 256>>>(X, cnt_se, N_E);
    // 21: combine GEMM
    sgemm2<2, false><<<cdiv(N_E, 128), 256>>>(
        X, 384, Wc, bc, C, 256, (float*)nullptr, 0, N_E, 384);
    // 22-23: BN
    bn_stats<<<256, 256>>>(C, N_E, sums, sumsq);
    bn_finalize<<<1, 256>>>(sums, sumsq, bn_gamma, bn_beta, scale, shift, 1.0f / (float)N_E);
    // 24: classifier
    classifier<<<cdiv(N_E * 32, 256), 256>>>(C, scale, shift, cls_base_w, cls_spline_w, out, N_E);
}